// round 9
// baseline (speedup 1.0000x reference)
#include <cuda_runtime.h>

#define NMAX 100000
#define EMAX 2000000
#define FSTRIDE 32          // feat/agg row stride in floats (128B rows; first 20 used)

// Scratch (__device__ globals; zero-initialized at load; every kernel restores
// the zero state of the accumulator it consumes -> graph replays deterministic)
__device__ __align__(128) float g_feat[NMAX * FSTRIDE];  // [x(3), emb(16), 0...]
__device__ __align__(128) float g_aggF[NMAX * FSTRIDE];  // layer-1 agg (zero in/out)
__device__ __align__(128) float g_bufA[NMAX * 32];       // h1@W2 messages for layer 2
__device__ __align__(128) float g_bufB[NMAX * 32];       // layer-2 agg (zero in/out)
__device__ float g_deg[NMAX];                            // weighted degree (zero in/out)
__device__ float g_dinv[NMAX];                           // rsqrt(deg+1)

// ---------------------------------------------------------------------------
// deg[col] += ew, 4 edges per thread (vectorized index/weight loads)
__global__ void deg_kernel(const int* __restrict__ col, const float* __restrict__ ew, int E4) {
    int t = blockIdx.x * blockDim.x + threadIdx.x;
    if (t >= E4) return;
    int4   c4 = ((const int4*)col)[t];
    float4 w4 = ((const float4*)ew)[t];
    atomicAdd(&g_deg[c4.x], w4.x);
    atomicAdd(&g_deg[c4.y], w4.y);
    atomicAdd(&g_deg[c4.z], w4.z);
    atomicAdd(&g_deg[c4.w], w4.w);
}

// ---------------------------------------------------------------------------
// Per-node: dinv = rsqrt(deg+1) (then deg := 0 for next replay);
// emb = relu(c@We1+be1)@We2+be2;  feat = [x, emb, pad] -> g_feat.
__global__ void embed_kernel(const float* __restrict__ x, const float* __restrict__ c,
                             const float* __restrict__ We1, const float* __restrict__ be1,
                             const float* __restrict__ We2, const float* __restrict__ be2,
                             int n) {
    __shared__ float4 sPack[128];   // {We1[0][j], We1[1][j], be1[j], 0}
    __shared__ float4 sWe2[512];    // [128][16] as float4
    __shared__ float  sbe2[16];

    for (int j = threadIdx.x; j < 128; j += blockDim.x)
        sPack[j] = make_float4(We1[j], We1[128 + j], be1[j], 0.f);
    for (int j = threadIdx.x; j < 512; j += blockDim.x)
        sWe2[j] = ((const float4*)We2)[j];
    if (threadIdx.x < 16) sbe2[threadIdx.x] = be2[threadIdx.x];
    __syncthreads();

    int i = blockIdx.x * blockDim.x + threadIdx.x;
    if (i >= n) return;

    g_dinv[i] = rsqrtf(g_deg[i] + 1.0f);   // self-loop weight 1 folded in
    g_deg[i]  = 0.0f;                      // restore zero state

    float c0 = c[2 * i], c1 = c[2 * i + 1];
    float emb[16];
#pragma unroll
    for (int k = 0; k < 16; k++) emb[k] = sbe2[k];

#pragma unroll 4
    for (int j = 0; j < 128; j++) {
        float4 p = sPack[j];
        float h = fmaxf(fmaf(c0, p.x, fmaf(c1, p.y, p.z)), 0.f);
#pragma unroll
        for (int q = 0; q < 4; q++) {
            float4 w = sWe2[j * 4 + q];
            emb[4 * q + 0] = fmaf(h, w.x, emb[4 * q + 0]);
            emb[4 * q + 1] = fmaf(h, w.y, emb[4 * q + 1]);
            emb[4 * q + 2] = fmaf(h, w.z, emb[4 * q + 2]);
            emb[4 * q + 3] = fmaf(h, w.w, emb[4 * q + 3]);
        }
    }

    float4* fp = (float4*)&g_feat[(size_t)i * FSTRIDE];
    fp[0] = make_float4(x[3 * i], x[3 * i + 1], x[3 * i + 2], emb[0]);
    fp[1] = make_float4(emb[1],  emb[2],  emb[3],  emb[4]);
    fp[2] = make_float4(emb[5],  emb[6],  emb[7],  emb[8]);
    fp[3] = make_float4(emb[9],  emb[10], emb[11], emb[12]);
    fp[4] = make_float4(emb[13], emb[14], emb[15], 0.f);
}

// ---------------------------------------------------------------------------
// Scatter layer 1: 5 threads per edge (all active), 128B-aligned 32-float rows,
// payload = first 5 float4 -> one L1 line per edge for gather and RED.
// aggF[col] += nrm * feat[row], nrm = dinv[r]*ew*dinv[c]
__global__ void scatter1_kernel(const int* __restrict__ ei, const float* __restrict__ ew, int E) {
    int t = blockIdx.x * blockDim.x + threadIdx.x;
    int e = t / 5;
    int q = t - e * 5;
    if (e >= E) return;
    int r = ei[e];
    int c = ei[E + e];
    float nrm = g_dinv[r] * ew[e] * g_dinv[c];
    float4 v = ((const float4*)g_feat)[(size_t)r * 8 + q];
    float vx = v.x * nrm, vy = v.y * nrm, vz = v.z * nrm, vw = v.w * nrm;
    float4* dst = ((float4*)g_aggF) + (size_t)c * 8 + q;
    asm volatile("red.global.add.v4.f32 [%0], {%1,%2,%3,%4};"
                 :: "l"(dst), "f"(vx), "f"(vy), "f"(vz), "f"(vw)
                 : "memory");
}

// ---------------------------------------------------------------------------
// Mid (warp-per-node, shfl matmuls): t = aggF + dinv^2*feat_self;
// h1 = relu(t@W1 + b1); bufA = h1@W2. Restores aggF and pre-zeroes bufB.
__global__ void mid_kernel(const float* __restrict__ W1, const float* __restrict__ b1,
                           const float* __restrict__ W2, int n) {
    __shared__ float sW1[608];   // [19][32]
    __shared__ float sW2[1024];  // [32][32]
    __shared__ float sb1[32];
    for (int j = threadIdx.x; j < 608; j += blockDim.x) sW1[j] = W1[j];
    for (int j = threadIdx.x; j < 1024; j += blockDim.x) sW2[j] = W2[j];
    if (threadIdx.x < 32) sb1[threadIdx.x] = b1[threadIdx.x];
    __syncthreads();

    int warp = (blockIdx.x * blockDim.x + threadIdx.x) >> 5;
    int lane = threadIdx.x & 31;
    if (warp >= n) return;
    int i = warp;

    float d = g_dinv[i];
    float s = d * d;
    float a = g_aggF[(size_t)i * FSTRIDE + lane];   // lanes >= 20 read zeros
    float f = g_feat[(size_t)i * FSTRIDE + lane];
    float tval = fmaf(s, f, a);                     // valid for lanes 0..18; rest unused
    if (lane < 20) g_aggF[(size_t)i * FSTRIDE + lane] = 0.f;   // restore zeros

    float h = sb1[lane];
#pragma unroll
    for (int r = 0; r < 19; r++)
        h = fmaf(__shfl_sync(0xffffffffu, tval, r), sW1[r * 32 + lane], h);
    h = fmaxf(h, 0.f);

    float o = 0.f;
#pragma unroll
    for (int m = 0; m < 32; m++)
        o = fmaf(__shfl_sync(0xffffffffu, h, m), sW2[m * 32 + lane], o);

    g_bufA[(size_t)i * 32 + lane] = o;
    g_bufB[(size_t)i * 32 + lane] = 0.f;   // pre-zero layer-2 agg target
}

// ---------------------------------------------------------------------------
// Scatter layer 2: 8 threads per edge over 32-wide bufA (at its RED lane floor).
__global__ void scatter2_kernel(const int* __restrict__ ei, const float* __restrict__ ew, int E) {
    int t = blockIdx.x * blockDim.x + threadIdx.x;
    int e = t >> 3;
    int q = t & 7;
    if (e >= E) return;
    int r = ei[e];
    int c = ei[E + e];
    float nrm = g_dinv[r] * ew[e] * g_dinv[c];
    float4 v = ((const float4*)g_bufA)[(size_t)r * 8 + q];
    float vx = v.x * nrm, vy = v.y * nrm, vz = v.z * nrm, vw = v.w * nrm;
    float4* dst = ((float4*)g_bufB) + (size_t)c * 8 + q;
    asm volatile("red.global.add.v4.f32 [%0], {%1,%2,%3,%4};"
                 :: "l"(dst), "f"(vx), "f"(vy), "f"(vz), "f"(vw)
                 : "memory");
}

// ---------------------------------------------------------------------------
// Final: h2 = relu(agg + dinv^2*xw + b2); out = h2 @ Wfc + bfc.
// Restores bufB to zero for the next replay.
__global__ void final_kernel(const float* __restrict__ b2, const float* __restrict__ Wfc,
                             const float* __restrict__ bfc, float* __restrict__ out, int n) {
    __shared__ float sWfc[32];
    __shared__ float sb2[32];
    __shared__ float sbfc;
    if (threadIdx.x < 32) { sWfc[threadIdx.x] = Wfc[threadIdx.x]; sb2[threadIdx.x] = b2[threadIdx.x]; }
    if (threadIdx.x == 0) sbfc = bfc[0];
    __syncthreads();

    int i = blockIdx.x * blockDim.x + threadIdx.x;
    if (i >= n) return;

    float d = g_dinv[i];
    float s = d * d;
    float4*       aggp = (float4*)&g_bufB[(size_t)i * 32];
    const float4* xwp  = (const float4*)&g_bufA[(size_t)i * 32];

    float acc = sbfc;
#pragma unroll
    for (int q = 0; q < 8; q++) {
        float4 a  = aggp[q];
        float4 xv = xwp[q];
        acc = fmaf(fmaxf(fmaf(s, xv.x, a.x) + sb2[4 * q + 0], 0.f), sWfc[4 * q + 0], acc);
        acc = fmaf(fmaxf(fmaf(s, xv.y, a.y) + sb2[4 * q + 1], 0.f), sWfc[4 * q + 1], acc);
        acc = fmaf(fmaxf(fmaf(s, xv.z, a.z) + sb2[4 * q + 2], 0.f), sWfc[4 * q + 2], acc);
        acc = fmaf(fmaxf(fmaf(s, xv.w, a.w) + sb2[4 * q + 3], 0.f), sWfc[4 * q + 3], acc);
        aggp[q] = make_float4(0.f, 0.f, 0.f, 0.f);   // restore zeros
    }
    out[i] = acc;
}

// ---------------------------------------------------------------------------
extern "C" void kernel_launch(void* const* d_in, const int* in_sizes, int n_in,
                              void* d_out, int out_size) {
    const float* x   = (const float*)d_in[0];
    const float* c   = (const float*)d_in[1];
    const int*   ei  = (const int*)d_in[2];
    const float* ew  = (const float*)d_in[3];
    const float* We1 = (const float*)d_in[4];
    const float* be1 = (const float*)d_in[5];
    const float* We2 = (const float*)d_in[6];
    const float* be2 = (const float*)d_in[7];
    const float* W1  = (const float*)d_in[8];
    const float* b1  = (const float*)d_in[9];
    const float* W2  = (const float*)d_in[10];
    const float* b2  = (const float*)d_in[11];
    const float* Wfc = (const float*)d_in[12];
    const float* bfc = (const float*)d_in[13];

    int n = in_sizes[1] / 2;   // c is [N, 2]
    int E = in_sizes[3];       // ew is [E]
    const int TB = 256;

    int E4 = E / 4;
    deg_kernel  <<<(E4 + TB - 1) / TB, TB>>>(ei + E, ew, E4);
    embed_kernel<<<(n + TB - 1) / TB, TB>>>(x, c, We1, be1, We2, be2, n);
    scatter1_kernel<<<((size_t)E * 5 + TB - 1) / TB, TB>>>(ei, ew, E);   // aligned 20-wide
    mid_kernel  <<<((size_t)n * 32 + TB - 1) / TB, TB>>>(W1, b1, W2, n); // warp per node
    scatter2_kernel<<<((size_t)E * 8 + TB - 1) / TB, TB>>>(ei, ew, E);   // 32-wide
    final_kernel<<<(n + TB - 1) / TB, TB>>>(b2, Wfc, bfc, (float*)d_out, n);
}

// round 10
// speedup vs baseline: 1.1885x; 1.1885x over previous
#include <cuda_runtime.h>

#define NMAX 100000
#define EMAX 2000000
#define FPAD 20            // feat width 19 padded to 20 (5 float4), dense rows (R7-proven)

// Scratch (__device__ globals; zero-initialized at load; every kernel restores
// the zero state of the accumulator it consumes -> graph replays deterministic)
__device__ __align__(128) float g_feat[NMAX * FPAD];  // [x(3), emb(16), 0]
__device__ __align__(128) float g_aggF[NMAX * FPAD];  // layer-1 agg (zero in/out)
__device__ __align__(128) float g_bufA[NMAX * 32];    // h1 messages for layer 2
__device__ __align__(128) float g_bufB[NMAX * 32];    // layer-2 agg (zero in/out)
__device__ float g_deg[NMAX];                         // weighted degree (zero in/out)
__device__ float g_dinv[NMAX];                        // rsqrt(deg+1)

// ---------------------------------------------------------------------------
// deg[col] += ew, 4 edges per thread (vectorized index/weight loads)
__global__ void deg_kernel(const int* __restrict__ col, const float* __restrict__ ew, int E4) {
    int t = blockIdx.x * blockDim.x + threadIdx.x;
    if (t >= E4) return;
    int4   c4 = ((const int4*)col)[t];
    float4 w4 = ((const float4*)ew)[t];
    atomicAdd(&g_deg[c4.x], w4.x);
    atomicAdd(&g_deg[c4.y], w4.y);
    atomicAdd(&g_deg[c4.z], w4.z);
    atomicAdd(&g_deg[c4.w], w4.w);
}

// ---------------------------------------------------------------------------
// Per-node: dinv = rsqrt(deg+1) (then deg := 0 for next replay);
// emb = relu(c@We1+be1)@We2+be2;  feat = [x, emb, 0] -> g_feat.
__global__ void embed_kernel(const float* __restrict__ x, const float* __restrict__ c,
                             const float* __restrict__ We1, const float* __restrict__ be1,
                             const float* __restrict__ We2, const float* __restrict__ be2,
                             int n) {
    __shared__ float4 sPack[128];   // {We1[0][j], We1[1][j], be1[j], 0}
    __shared__ float4 sWe2[512];    // [128][16] as float4
    __shared__ float  sbe2[16];

    for (int j = threadIdx.x; j < 128; j += blockDim.x)
        sPack[j] = make_float4(We1[j], We1[128 + j], be1[j], 0.f);
    for (int j = threadIdx.x; j < 512; j += blockDim.x)
        sWe2[j] = ((const float4*)We2)[j];
    if (threadIdx.x < 16) sbe2[threadIdx.x] = be2[threadIdx.x];
    __syncthreads();

    int i = blockIdx.x * blockDim.x + threadIdx.x;
    if (i >= n) return;

    g_dinv[i] = rsqrtf(g_deg[i] + 1.0f);   // self-loop weight 1 folded in
    g_deg[i]  = 0.0f;                      // restore zero state

    float c0 = c[2 * i], c1 = c[2 * i + 1];
    float emb[16];
#pragma unroll
    for (int k = 0; k < 16; k++) emb[k] = sbe2[k];

#pragma unroll 4
    for (int j = 0; j < 128; j++) {
        float4 p = sPack[j];
        float h = fmaxf(fmaf(c0, p.x, fmaf(c1, p.y, p.z)), 0.f);
#pragma unroll
        for (int q = 0; q < 4; q++) {
            float4 w = sWe2[j * 4 + q];
            emb[4 * q + 0] = fmaf(h, w.x, emb[4 * q + 0]);
            emb[4 * q + 1] = fmaf(h, w.y, emb[4 * q + 1]);
            emb[4 * q + 2] = fmaf(h, w.z, emb[4 * q + 2]);
            emb[4 * q + 3] = fmaf(h, w.w, emb[4 * q + 3]);
        }
    }

    float4* fp = (float4*)&g_feat[(size_t)i * FPAD];
    fp[0] = make_float4(x[3 * i], x[3 * i + 1], x[3 * i + 2], emb[0]);
    fp[1] = make_float4(emb[1],  emb[2],  emb[3],  emb[4]);
    fp[2] = make_float4(emb[5],  emb[6],  emb[7],  emb[8]);
    fp[3] = make_float4(emb[9],  emb[10], emb[11], emb[12]);
    fp[4] = make_float4(emb[13], emb[14], emb[15], 0.f);
}

// ---------------------------------------------------------------------------
// Scatter layer 1: 5 threads per edge over dense 20-wide feat rows (R7-proven).
// aggF[col] += nrm * feat[row], nrm = dinv[r]*ew*dinv[c]
__global__ void scatter1_kernel(const int* __restrict__ ei, const float* __restrict__ ew, int E) {
    int t = blockIdx.x * blockDim.x + threadIdx.x;
    int e = t / 5;
    int q = t - e * 5;
    if (e >= E) return;
    int r = ei[e];
    int c = ei[E + e];
    float nrm = g_dinv[r] * ew[e] * g_dinv[c];
    float4 v = ((const float4*)g_feat)[(size_t)r * 5 + q];
    float vx = v.x * nrm, vy = v.y * nrm, vz = v.z * nrm, vw = v.w * nrm;
    float4* dst = ((float4*)g_aggF) + (size_t)c * 5 + q;
    asm volatile("red.global.add.v4.f32 [%0], {%1,%2,%3,%4};"
                 :: "l"(dst), "f"(vx), "f"(vy), "f"(vz), "f"(vw)
                 : "memory");
}

// ---------------------------------------------------------------------------
// Mid (streaming single matmul): t = aggF + dinv^2*feat_self, consumed 4-at-a-
// time into h1 = relu(t@W1 + b1). Stores h1 (32-wide) to bufA for scatter2.
// Restores aggF zeros and pre-zeroes bufB. Only acc[32] live -> low regs.
__global__ void mid_kernel(const float* __restrict__ W1, const float* __restrict__ b1, int n) {
    __shared__ float4 sW1[152];  // [19][32] as float4
    __shared__ float  sb1[32];
    for (int j = threadIdx.x; j < 152; j += blockDim.x) sW1[j] = ((const float4*)W1)[j];
    if (threadIdx.x < 32) sb1[threadIdx.x] = b1[threadIdx.x];
    __syncthreads();

    int i = blockIdx.x * blockDim.x + threadIdx.x;
    if (i >= n) return;

    float d = g_dinv[i];
    float s = d * d;
    float4*       aggp = (float4*)&g_aggF[(size_t)i * FPAD];
    const float4* fp   = (const float4*)&g_feat[(size_t)i * FPAD];

    float4 acc[8];
#pragma unroll
    for (int q = 0; q < 8; q++)
        acc[q] = make_float4(sb1[4*q], sb1[4*q+1], sb1[4*q+2], sb1[4*q+3]);

#pragma unroll
    for (int c4 = 0; c4 < 5; c4++) {
        float4 a = aggp[c4];
        float4 f = fp[c4];
        aggp[c4] = make_float4(0.f, 0.f, 0.f, 0.f);   // restore zeros
        float tv[4] = { fmaf(s, f.x, a.x), fmaf(s, f.y, a.y),
                        fmaf(s, f.z, a.z), fmaf(s, f.w, a.w) };
#pragma unroll
        for (int j = 0; j < 4; j++) {
            int r = c4 * 4 + j;
            if (r < 19) {
                float t = tv[j];
#pragma unroll
                for (int q = 0; q < 8; q++) {
                    float4 w = sW1[r * 8 + q];
                    acc[q].x = fmaf(t, w.x, acc[q].x);
                    acc[q].y = fmaf(t, w.y, acc[q].y);
                    acc[q].z = fmaf(t, w.z, acc[q].z);
                    acc[q].w = fmaf(t, w.w, acc[q].w);
                }
            }
        }
    }

    float4* outp = (float4*)&g_bufA[(size_t)i * 32];
    float4* zp   = (float4*)&g_bufB[(size_t)i * 32];
#pragma unroll
    for (int q = 0; q < 8; q++) {
        outp[q] = make_float4(fmaxf(acc[q].x, 0.f), fmaxf(acc[q].y, 0.f),
                              fmaxf(acc[q].z, 0.f), fmaxf(acc[q].w, 0.f));
        zp[q]   = make_float4(0.f, 0.f, 0.f, 0.f);   // pre-zero layer-2 agg
    }
}

// ---------------------------------------------------------------------------
// Scatter layer 2: 8 threads per edge over 32-wide h1 (RED lane floor).
__global__ void scatter2_kernel(const int* __restrict__ ei, const float* __restrict__ ew, int E) {
    int t = blockIdx.x * blockDim.x + threadIdx.x;
    int e = t >> 3;
    int q = t & 7;
    if (e >= E) return;
    int r = ei[e];
    int c = ei[E + e];
    float nrm = g_dinv[r] * ew[e] * g_dinv[c];
    float4 v = ((const float4*)g_bufA)[(size_t)r * 8 + q];
    float vx = v.x * nrm, vy = v.y * nrm, vz = v.z * nrm, vw = v.w * nrm;
    float4* dst = ((float4*)g_bufB) + (size_t)c * 8 + q;
    asm volatile("red.global.add.v4.f32 [%0], {%1,%2,%3,%4};"
                 :: "l"(dst), "f"(vx), "f"(vy), "f"(vz), "f"(vw)
                 : "memory");
}

// ---------------------------------------------------------------------------
// Final (streaming W2 matmul, applied POST-aggregation via linearity):
// u = aggB + dinv^2*h1_self (consumed 4-at-a-time); h2 = relu(u@W2 + b2);
// out = h2 @ Wfc + bfc. Restores bufB zeros.
__global__ void final_kernel(const float* __restrict__ W2, const float* __restrict__ b2,
                             const float* __restrict__ Wfc, const float* __restrict__ bfc,
                             float* __restrict__ out, int n) {
    __shared__ float4 sW2[256];  // [32][32] as float4
    __shared__ float  sb2[32];
    __shared__ float  sWfc[32];
    __shared__ float  sbfc;
    for (int j = threadIdx.x; j < 256; j += blockDim.x) sW2[j] = ((const float4*)W2)[j];
    if (threadIdx.x < 32) { sb2[threadIdx.x] = b2[threadIdx.x]; sWfc[threadIdx.x] = Wfc[threadIdx.x]; }
    if (threadIdx.x == 0) sbfc = bfc[0];
    __syncthreads();

    int i = blockIdx.x * blockDim.x + threadIdx.x;
    if (i >= n) return;

    float d = g_dinv[i];
    float s = d * d;
    float4*       aggp = (float4*)&g_bufB[(size_t)i * 32];
    const float4* hp   = (const float4*)&g_bufA[(size_t)i * 32];

    float4 acc[8];
#pragma unroll
    for (int q = 0; q < 8; q++)
        acc[q] = make_float4(sb2[4*q], sb2[4*q+1], sb2[4*q+2], sb2[4*q+3]);

#pragma unroll
    for (int c4 = 0; c4 < 8; c4++) {
        float4 a = aggp[c4];
        float4 h = hp[c4];
        aggp[c4] = make_float4(0.f, 0.f, 0.f, 0.f);   // restore zeros
        float uv[4] = { fmaf(s, h.x, a.x), fmaf(s, h.y, a.y),
                        fmaf(s, h.z, a.z), fmaf(s, h.w, a.w) };
#pragma unroll
        for (int j = 0; j < 4; j++) {
            int m = c4 * 4 + j;
            float u = uv[j];
#pragma unroll
            for (int q = 0; q < 8; q++) {
                float4 w = sW2[m * 8 + q];
                acc[q].x = fmaf(u, w.x, acc[q].x);
                acc[q].y = fmaf(u, w.y, acc[q].y);
                acc[q].z = fmaf(u, w.z, acc[q].z);
                acc[q].w = fmaf(u, w.w, acc[q].w);
            }
        }
    }

    float o = sbfc;
#pragma unroll
    for (int q = 0; q < 8; q++) {
        o = fmaf(fmaxf(acc[q].x, 0.f), sWfc[4*q+0], o);
        o = fmaf(fmaxf(acc[q].y, 0.f), sWfc[4*q+1], o);
        o = fmaf(fmaxf(acc[q].z, 0.f), sWfc[4*q+2], o);
        o = fmaf(fmaxf(acc[q].w, 0.f), sWfc[4*q+3], o);
    }
    out[i] = o;
}

// ---------------------------------------------------------------------------
extern "C" void kernel_launch(void* const* d_in, const int* in_sizes, int n_in,
                              void* d_out, int out_size) {
    const float* x   = (const float*)d_in[0];
    const float* c   = (const float*)d_in[1];
    const int*   ei  = (const int*)d_in[2];
    const float* ew  = (const float*)d_in[3];
    const float* We1 = (const float*)d_in[4];
    const float* be1 = (const float*)d_in[5];
    const float* We2 = (const float*)d_in[6];
    const float* be2 = (const float*)d_in[7];
    const float* W1  = (const float*)d_in[8];
    const float* b1  = (const float*)d_in[9];
    const float* W2  = (const float*)d_in[10];
    const float* b2  = (const float*)d_in[11];
    const float* Wfc = (const float*)d_in[12];
    const float* bfc = (const float*)d_in[13];

    int n = in_sizes[1] / 2;   // c is [N, 2]
    int E = in_sizes[3];       // ew is [E]
    const int TB = 256;

    int E4 = E / 4;
    deg_kernel  <<<(E4 + TB - 1) / TB, TB>>>(ei + E, ew, E4);
    embed_kernel<<<(n + TB - 1) / TB, TB>>>(x, c, We1, be1, We2, be2, n);
    scatter1_kernel<<<((size_t)E * 5 + TB - 1) / TB, TB>>>(ei, ew, E);   // 20-wide feat
    mid_kernel  <<<(n + TB - 1) / TB, TB>>>(W1, b1, n);                  // t@W1 only
    scatter2_kernel<<<((size_t)E * 8 + TB - 1) / TB, TB>>>(ei, ew, E);   // 32-wide h1
    final_kernel<<<(n + TB - 1) / TB, TB>>>(W2, b2, Wfc, bfc, (float*)d_out, n);
}

// round 11
// speedup vs baseline: 1.1887x; 1.0002x over previous
#include <cuda_runtime.h>

#define NMAX 100000
#define EMAX 2000000
#define FPAD 20            // feat width 19 padded to 20 (5 float4), dense rows (R7-proven)

// Scratch (__device__ globals; zero-initialized at load; every kernel restores
// the zero state of the accumulator it consumes -> graph replays deterministic)
__device__ __align__(128) float g_feat[NMAX * FPAD];  // [x(3), emb(16), 0]
__device__ __align__(128) float g_aggF[NMAX * FPAD];  // layer-1 agg (zero in/out)
__device__ __align__(128) float g_bufA[NMAX * 32];    // h1 messages for layer 2
__device__ __align__(128) float g_bufB[NMAX * 32];    // layer-2 agg (zero in/out)
__device__ float g_deg[NMAX];                         // weighted degree (zero in/out)
__device__ float g_dinv[NMAX];                        // rsqrt(deg+1)

// ---------------------------------------------------------------------------
// deg[col] += ew, 4 edges per thread (vectorized index/weight loads)
__global__ void deg_kernel(const int* __restrict__ col, const float* __restrict__ ew, int E4) {
    int t = blockIdx.x * blockDim.x + threadIdx.x;
    if (t >= E4) return;
    int4   c4 = ((const int4*)col)[t];
    float4 w4 = ((const float4*)ew)[t];
    atomicAdd(&g_deg[c4.x], w4.x);
    atomicAdd(&g_deg[c4.y], w4.y);
    atomicAdd(&g_deg[c4.z], w4.z);
    atomicAdd(&g_deg[c4.w], w4.w);
}

// ---------------------------------------------------------------------------
// Per-node: dinv = rsqrt(deg+1) (then deg := 0 for next replay);
// emb = relu(c@We1+be1)@We2+be2;  feat = [x, emb, 0] -> g_feat.
__global__ void embed_kernel(const float* __restrict__ x, const float* __restrict__ c,
                             const float* __restrict__ We1, const float* __restrict__ be1,
                             const float* __restrict__ We2, const float* __restrict__ be2,
                             int n) {
    __shared__ float4 sPack[128];   // {We1[0][j], We1[1][j], be1[j], 0}
    __shared__ float4 sWe2[512];    // [128][16] as float4
    __shared__ float  sbe2[16];

    for (int j = threadIdx.x; j < 128; j += blockDim.x)
        sPack[j] = make_float4(We1[j], We1[128 + j], be1[j], 0.f);
    for (int j = threadIdx.x; j < 512; j += blockDim.x)
        sWe2[j] = ((const float4*)We2)[j];
    if (threadIdx.x < 16) sbe2[threadIdx.x] = be2[threadIdx.x];
    __syncthreads();

    int i = blockIdx.x * blockDim.x + threadIdx.x;
    if (i >= n) return;

    g_dinv[i] = rsqrtf(g_deg[i] + 1.0f);   // self-loop weight 1 folded in
    g_deg[i]  = 0.0f;                      // restore zero state

    float c0 = c[2 * i], c1 = c[2 * i + 1];
    float emb[16];
#pragma unroll
    for (int k = 0; k < 16; k++) emb[k] = sbe2[k];

#pragma unroll 4
    for (int j = 0; j < 128; j++) {
        float4 p = sPack[j];
        float h = fmaxf(fmaf(c0, p.x, fmaf(c1, p.y, p.z)), 0.f);
#pragma unroll
        for (int q = 0; q < 4; q++) {
            float4 w = sWe2[j * 4 + q];
            emb[4 * q + 0] = fmaf(h, w.x, emb[4 * q + 0]);
            emb[4 * q + 1] = fmaf(h, w.y, emb[4 * q + 1]);
            emb[4 * q + 2] = fmaf(h, w.z, emb[4 * q + 2]);
            emb[4 * q + 3] = fmaf(h, w.w, emb[4 * q + 3]);
        }
    }

    float4* fp = (float4*)&g_feat[(size_t)i * FPAD];
    fp[0] = make_float4(x[3 * i], x[3 * i + 1], x[3 * i + 2], emb[0]);
    fp[1] = make_float4(emb[1],  emb[2],  emb[3],  emb[4]);
    fp[2] = make_float4(emb[5],  emb[6],  emb[7],  emb[8]);
    fp[3] = make_float4(emb[9],  emb[10], emb[11], emb[12]);
    fp[4] = make_float4(emb[13], emb[14], emb[15], 0.f);
}

// ---------------------------------------------------------------------------
// Scatter layer 1: 5 threads per edge over dense 20-wide feat rows (R7-proven).
// aggF[col] += nrm * feat[row], nrm = dinv[r]*ew*dinv[c]
__global__ void scatter1_kernel(const int* __restrict__ ei, const float* __restrict__ ew, int E) {
    int t = blockIdx.x * blockDim.x + threadIdx.x;
    int e = t / 5;
    int q = t - e * 5;
    if (e >= E) return;
    int r = ei[e];
    int c = ei[E + e];
    float nrm = g_dinv[r] * ew[e] * g_dinv[c];
    float4 v = ((const float4*)g_feat)[(size_t)r * 5 + q];
    float vx = v.x * nrm, vy = v.y * nrm, vz = v.z * nrm, vw = v.w * nrm;
    float4* dst = ((float4*)g_aggF) + (size_t)c * 5 + q;
    asm volatile("red.global.add.v4.f32 [%0], {%1,%2,%3,%4};"
                 :: "l"(dst), "f"(vx), "f"(vy), "f"(vz), "f"(vw)
                 : "memory");
}

// ---------------------------------------------------------------------------
// Mid (streaming single matmul): t = aggF + dinv^2*feat_self, consumed 4-at-a-
// time into h1 = relu(t@W1 + b1). Stores h1 (32-wide) to bufA for scatter2.
// Restores aggF zeros and pre-zeroes bufB. Only acc[32] live -> low regs.
__global__ void mid_kernel(const float* __restrict__ W1, const float* __restrict__ b1, int n) {
    __shared__ float4 sW1[152];  // [19][32] as float4
    __shared__ float  sb1[32];
    for (int j = threadIdx.x; j < 152; j += blockDim.x) sW1[j] = ((const float4*)W1)[j];
    if (threadIdx.x < 32) sb1[threadIdx.x] = b1[threadIdx.x];
    __syncthreads();

    int i = blockIdx.x * blockDim.x + threadIdx.x;
    if (i >= n) return;

    float d = g_dinv[i];
    float s = d * d;
    float4*       aggp = (float4*)&g_aggF[(size_t)i * FPAD];
    const float4* fp   = (const float4*)&g_feat[(size_t)i * FPAD];

    float4 acc[8];
#pragma unroll
    for (int q = 0; q < 8; q++)
        acc[q] = make_float4(sb1[4*q], sb1[4*q+1], sb1[4*q+2], sb1[4*q+3]);

#pragma unroll
    for (int c4 = 0; c4 < 5; c4++) {
        float4 a = aggp[c4];
        float4 f = fp[c4];
        aggp[c4] = make_float4(0.f, 0.f, 0.f, 0.f);   // restore zeros
        float tv[4] = { fmaf(s, f.x, a.x), fmaf(s, f.y, a.y),
                        fmaf(s, f.z, a.z), fmaf(s, f.w, a.w) };
#pragma unroll
        for (int j = 0; j < 4; j++) {
            int r = c4 * 4 + j;
            if (r < 19) {
                float t = tv[j];
#pragma unroll
                for (int q = 0; q < 8; q++) {
                    float4 w = sW1[r * 8 + q];
                    acc[q].x = fmaf(t, w.x, acc[q].x);
                    acc[q].y = fmaf(t, w.y, acc[q].y);
                    acc[q].z = fmaf(t, w.z, acc[q].z);
                    acc[q].w = fmaf(t, w.w, acc[q].w);
                }
            }
        }
    }

    float4* outp = (float4*)&g_bufA[(size_t)i * 32];
    float4* zp   = (float4*)&g_bufB[(size_t)i * 32];
#pragma unroll
    for (int q = 0; q < 8; q++) {
        outp[q] = make_float4(fmaxf(acc[q].x, 0.f), fmaxf(acc[q].y, 0.f),
                              fmaxf(acc[q].z, 0.f), fmaxf(acc[q].w, 0.f));
        zp[q]   = make_float4(0.f, 0.f, 0.f, 0.f);   // pre-zero layer-2 agg
    }
}

// ---------------------------------------------------------------------------
// Scatter layer 2: 8 threads per edge over 32-wide h1 (RED lane floor).
__global__ void scatter2_kernel(const int* __restrict__ ei, const float* __restrict__ ew, int E) {
    int t = blockIdx.x * blockDim.x + threadIdx.x;
    int e = t >> 3;
    int q = t & 7;
    if (e >= E) return;
    int r = ei[e];
    int c = ei[E + e];
    float nrm = g_dinv[r] * ew[e] * g_dinv[c];
    float4 v = ((const float4*)g_bufA)[(size_t)r * 8 + q];
    float vx = v.x * nrm, vy = v.y * nrm, vz = v.z * nrm, vw = v.w * nrm;
    float4* dst = ((float4*)g_bufB) + (size_t)c * 8 + q;
    asm volatile("red.global.add.v4.f32 [%0], {%1,%2,%3,%4};"
                 :: "l"(dst), "f"(vx), "f"(vy), "f"(vz), "f"(vw)
                 : "memory");
}

// ---------------------------------------------------------------------------
// Final (streaming W2 matmul, applied POST-aggregation via linearity):
// u = aggB + dinv^2*h1_self (consumed 4-at-a-time); h2 = relu(u@W2 + b2);
// out = h2 @ Wfc + bfc. Restores bufB zeros.
__global__ void final_kernel(const float* __restrict__ W2, const float* __restrict__ b2,
                             const float* __restrict__ Wfc, const float* __restrict__ bfc,
                             float* __restrict__ out, int n) {
    __shared__ float4 sW2[256];  // [32][32] as float4
    __shared__ float  sb2[32];
    __shared__ float  sWfc[32];
    __shared__ float  sbfc;
    for (int j = threadIdx.x; j < 256; j += blockDim.x) sW2[j] = ((const float4*)W2)[j];
    if (threadIdx.x < 32) { sb2[threadIdx.x] = b2[threadIdx.x]; sWfc[threadIdx.x] = Wfc[threadIdx.x]; }
    if (threadIdx.x == 0) sbfc = bfc[0];
    __syncthreads();

    int i = blockIdx.x * blockDim.x + threadIdx.x;
    if (i >= n) return;

    float d = g_dinv[i];
    float s = d * d;
    float4*       aggp = (float4*)&g_bufB[(size_t)i * 32];
    const float4* hp   = (const float4*)&g_bufA[(size_t)i * 32];

    float4 acc[8];
#pragma unroll
    for (int q = 0; q < 8; q++)
        acc[q] = make_float4(sb2[4*q], sb2[4*q+1], sb2[4*q+2], sb2[4*q+3]);

#pragma unroll
    for (int c4 = 0; c4 < 8; c4++) {
        float4 a = aggp[c4];
        float4 h = hp[c4];
        aggp[c4] = make_float4(0.f, 0.f, 0.f, 0.f);   // restore zeros
        float uv[4] = { fmaf(s, h.x, a.x), fmaf(s, h.y, a.y),
                        fmaf(s, h.z, a.z), fmaf(s, h.w, a.w) };
#pragma unroll
        for (int j = 0; j < 4; j++) {
            int m = c4 * 4 + j;
            float u = uv[j];
#pragma unroll
            for (int q = 0; q < 8; q++) {
                float4 w = sW2[m * 8 + q];
                acc[q].x = fmaf(u, w.x, acc[q].x);
                acc[q].y = fmaf(u, w.y, acc[q].y);
                acc[q].z = fmaf(u, w.z, acc[q].z);
                acc[q].w = fmaf(u, w.w, acc[q].w);
            }
        }
    }

    float o = sbfc;
#pragma unroll
    for (int q = 0; q < 8; q++) {
        o = fmaf(fmaxf(acc[q].x, 0.f), sWfc[4*q+0], o);
        o = fmaf(fmaxf(acc[q].y, 0.f), sWfc[4*q+1], o);
        o = fmaf(fmaxf(acc[q].z, 0.f), sWfc[4*q+2], o);
        o = fmaf(fmaxf(acc[q].w, 0.f), sWfc[4*q+3], o);
    }
    out[i] = o;
}

// ---------------------------------------------------------------------------
extern "C" void kernel_launch(void* const* d_in, const int* in_sizes, int n_in,
                              void* d_out, int out_size) {
    const float* x   = (const float*)d_in[0];
    const float* c   = (const float*)d_in[1];
    const int*   ei  = (const int*)d_in[2];
    const float* ew  = (const float*)d_in[3];
    const float* We1 = (const float*)d_in[4];
    const float* be1 = (const float*)d_in[5];
    const float* We2 = (const float*)d_in[6];
    const float* be2 = (const float*)d_in[7];
    const float* W1  = (const float*)d_in[8];
    const float* b1  = (const float*)d_in[9];
    const float* W2  = (const float*)d_in[10];
    const float* b2  = (const float*)d_in[11];
    const float* Wfc = (const float*)d_in[12];
    const float* bfc = (const float*)d_in[13];

    int n = in_sizes[1] / 2;   // c is [N, 2]
    int E = in_sizes[3];       // ew is [E]
    const int TB = 256;

    int E4 = E / 4;
    deg_kernel  <<<(E4 + TB - 1) / TB, TB>>>(ei + E, ew, E4);
    embed_kernel<<<(n + TB - 1) / TB, TB>>>(x, c, We1, be1, We2, be2, n);
    scatter1_kernel<<<((size_t)E * 5 + TB - 1) / TB, TB>>>(ei, ew, E);   // 20-wide feat
    mid_kernel  <<<(n + TB - 1) / TB, TB>>>(W1, b1, n);                  // t@W1 only
    scatter2_kernel<<<((size_t)E * 8 + TB - 1) / TB, TB>>>(ei, ew, E);   // 32-wide h1
    final_kernel<<<(n + TB - 1) / TB, TB>>>(W2, b2, Wfc, bfc, (float*)d_out, n);
}